// round 14
// baseline (speedup 1.0000x reference)
#include <cuda_runtime.h>
#include <cuda_bf16.h>
#include <math.h>

#define NN 50000
#define EE 1600000
#define KCH 5

// ---------------- static scratch (no runtime allocation) ----------------
__device__ int   g_is64;           // edge_index dtype flag (detected on device)
__device__ float g_deg[NN];        // degree -> rsqrt(deg) in-place
__device__ int   g_cnt[NN];        // histogram of in-degree (by col)
__device__ int   g_fill[NN];       // fill cursors for CSR scatter
__device__ int   g_ptr[NN + 1];    // CSR row (target) pointers
__device__ int   g_r32[EE];        // edge source (int32)
__device__ int   g_c32[EE];        // edge target (int32)
__device__ float g_wn[EE];         // normalized edge weight (unsorted)
__device__ int2  g_edge[EE];       // CSR: packed (source row, weight-as-int) per entry
__device__ float g_T0[NN * 32];
__device__ float g_T1[NN * 32];
__device__ float g_T2[NN * 32];
__device__ float g_Az[NN * 32];
__device__ float g_Ah[NN * 32];
__device__ float g_h1[NN * 32];
__device__ float g_h2[NN * 16];

static const unsigned FULL = 0xFFFFFFFFu;

// selector -> device buffer (avoids host symbol queries)
__device__ __forceinline__ float* selbuf(int s) {
    switch (s) {
        case 0: return g_T0;
        case 1: return g_T1;
        case 2: return g_T2;
        case 5: return g_h1;
        case 6: return g_h2;
    }
    return g_T0;
}

// ---------------- dtype detection: int64 edge_index has all-zero odd words ----
__global__ void detect_kernel(const int* __restrict__ ei32) {
    __shared__ int snz;
    if (threadIdx.x == 0) snz = 0;
    __syncthreads();
    int v = 0;
    for (int i = threadIdx.x; i < 65536; i += blockDim.x) v |= ei32[2 * i + 1];
    if (v) atomicOr(&snz, 1);
    __syncthreads();
    if (threadIdx.x == 0) g_is64 = (snz == 0) ? 1 : 0;
}

// ---------------- zero-init (graph-safe) ----------------
__global__ void zero_init_kernel() {
    int i = blockIdx.x * blockDim.x + threadIdx.x;
    if (i < NN) {
        g_deg[i]  = 0.0f;
        g_cnt[i]  = 0;
        g_fill[i] = 0;
    }
}

// ---------------- edge preprocessing ----------------
__global__ void edge_deg_kernel(const int* __restrict__ ei32,
                                const float* __restrict__ ew) {
    int e = blockIdx.x * blockDim.x + threadIdx.x;
    if (e >= EE) return;
    int r, c;
    if (g_is64) {   // int64 little-endian: value in even word
        r = ei32[2 * e];
        c = ei32[2 * (EE + e)];
    } else {        // int32
        r = ei32[e];
        c = ei32[EE + e];
    }
    r = min(max(r, 0), NN - 1);
    c = min(max(c, 0), NN - 1);
    g_r32[e] = r;
    g_c32[e] = c;
    atomicAdd(&g_deg[r], ew[e]);
}

__global__ void node_dis_kernel() {
    int n = blockIdx.x * blockDim.x + threadIdx.x;
    if (n >= NN) return;
    float d = g_deg[n];
    g_deg[n] = (d > 0.0f) ? rsqrtf(d) : 0.0f;
}

__global__ void edge_wn_kernel(const float* __restrict__ ew) {
    int e = blockIdx.x * blockDim.x + threadIdx.x;
    if (e >= EE) return;
    int r = g_r32[e];
    int c = g_c32[e];
    g_wn[e] = -g_deg[r] * ew[e] * g_deg[c];
    atomicAdd(&g_cnt[c], 1);
}

// single-block exclusive scan over g_cnt -> g_ptr (warp-shuffle based)
__global__ void scan_kernel() {
    __shared__ int wsum[32];
    __shared__ int carry_s;
    int tid = threadIdx.x, lane = tid & 31, wid = tid >> 5;
    if (tid == 0) carry_s = 0;
    __syncthreads();
    for (int base = 0; base < NN; base += 1024) {
        int i = base + tid;
        int v = (i < NN) ? g_cnt[i] : 0;
        int x = v;
        #pragma unroll
        for (int off = 1; off < 32; off <<= 1) {
            int t = __shfl_up_sync(FULL, x, off);
            if (lane >= off) x += t;
        }
        if (lane == 31) wsum[wid] = x;
        __syncthreads();
        if (wid == 0) {
            int y = wsum[lane];
            #pragma unroll
            for (int off = 1; off < 32; off <<= 1) {
                int t = __shfl_up_sync(FULL, y, off);
                if (lane >= off) y += t;
            }
            wsum[lane] = y;
        }
        __syncthreads();
        int incl = x + (wid > 0 ? wsum[wid - 1] : 0) + carry_s;
        if (i < NN) g_ptr[i + 1] = incl;
        __syncthreads();
        if (tid == 1023) carry_s = incl;
        __syncthreads();
    }
    if (tid == 0) g_ptr[0] = 0;
}

__global__ void edge_fill_kernel() {
    int e = blockIdx.x * blockDim.x + threadIdx.x;
    if (e >= EE) return;
    int c = g_c32[e];
    int pos = g_ptr[c] + atomicAdd(&g_fill[c], 1);
    g_edge[pos] = make_int2(g_r32[e], __float_as_int(g_wn[e]));
}

// ---------------- k=0 term: g_Az/g_Ah = bias + Tin @ W[0] ----------------
__global__ __launch_bounds__(256) void gemm0_kernel(
    const float* __restrict__ TinExt, int selTin,
    const float* __restrict__ Wz, const float* __restrict__ Wh,
    const float* __restrict__ bxz, const float* __restrict__ bhz,
    const float* __restrict__ bxh, const float* __restrict__ bhh, int FO) {
    __shared__ float sWz[1024];
    __shared__ float sWh[1024];
    const float* Tin = (selTin < 0) ? TinExt : selbuf(selTin);
    int tid = threadIdx.x;
    for (int i = tid; i < 32 * FO; i += blockDim.x) { sWz[i] = Wz[i]; sWh[i] = Wh[i]; }
    __syncthreads();
    int warp = (blockIdx.x * blockDim.x + tid) >> 5;
    int lane = tid & 31;
    if (warp >= NN) return;
    float t = Tin[warp * 32 + lane];
    float az = 0.0f, ah = 0.0f;
    #pragma unroll
    for (int fi = 0; fi < 32; fi++) {
        float v = __shfl_sync(FULL, t, fi);
        az = fmaf(v, sWz[fi * FO + lane], az);
        ah = fmaf(v, sWh[fi * FO + lane], ah);
    }
    if (lane < FO) {
        g_Az[warp * FO + lane] = az + bxz[lane] + bhz[lane];
        g_Ah[warp * FO + lane] = ah + bxh[lane] + bhh[lane];
    }
}

// ---------------- SpMM (CSR gather, 16-way MLP, broadcast edge reads) ----------------
// warp per target node; lane = feature. selPrev == -2 -> first (Tnew = L@Tin),
// selPrev == -1 -> prev is PrevExt, else prev = selbuf(selPrev).
__global__ __launch_bounds__(256) void spmm_gate_kernel(
    const float* __restrict__ TinExt, int selTin,
    const float* __restrict__ PrevExt, int selPrev, int selOut,
    const float* __restrict__ Wz, const float* __restrict__ Wh, int FO) {
    __shared__ float sWz[1024];
    __shared__ float sWh[1024];
    const float* Tin  = (selTin < 0) ? TinExt : selbuf(selTin);
    float*       Tout = selbuf(selOut);
    int tid = threadIdx.x;
    for (int i = tid; i < 32 * FO; i += blockDim.x) { sWz[i] = Wz[i]; sWh[i] = Wh[i]; }
    __syncthreads();
    int warp = (blockIdx.x * blockDim.x + tid) >> 5;
    int lane = tid & 31;
    if (warp >= NN) return;
    int s = g_ptr[warp];
    int e = g_ptr[warp + 1];
    float acc = 0.0f;
    const int2* __restrict__ ep = g_edge;
    for (int base = s; base < e; base += 16) {
        // 16 broadcast edge loads (uniform address per j -> 1 wavefront, L1-resident),
        // then 16 independent row gathers, then 16 FMAs.
        float ww[16];
        float vv[16];
        #pragma unroll
        for (int u = 0; u < 16; u++) {
            int  idx = base + u;
            bool ok  = idx < e;
            int2 ed  = ep[ok ? idx : s];   // s < e guaranteed (loop entered)
            ww[u] = ok ? __int_as_float(ed.y) : 0.0f;
            vv[u] = Tin[ed.x * 32 + lane];
        }
        #pragma unroll
        for (int u = 0; u < 16; u++) acc = fmaf(ww[u], vv[u], acc);
    }
    float tnew;
    if (selPrev == -2) {
        tnew = acc;
    } else {
        const float* Tprev = (selPrev == -1) ? PrevExt : selbuf(selPrev);
        tnew = 2.0f * acc - Tprev[warp * 32 + lane];
    }
    Tout[warp * 32 + lane] = tnew;
    float az = 0.0f, ah = 0.0f;
    #pragma unroll
    for (int fi = 0; fi < 32; fi++) {
        float v = __shfl_sync(FULL, tnew, fi);
        az = fmaf(v, sWz[fi * FO + lane], az);
        ah = fmaf(v, sWh[fi * FO + lane], ah);
    }
    if (lane < FO) {
        g_Az[warp * FO + lane] += az;
        g_Ah[warp * FO + lane] += ah;
    }
}

// ---------------- gate nonlinearity: h = relu((1-sigmoid(Az)) * tanh(Ah)) ----------------
__global__ void gate_final_kernel(int selOut, int total) {
    int i = blockIdx.x * blockDim.x + threadIdx.x;
    if (i >= total) return;
    float* h = selbuf(selOut);
    float z = 1.0f / (1.0f + expf(-g_Az[i]));
    float v = (1.0f - z) * tanhf(g_Ah[i]);
    h[i] = fmaxf(v, 0.0f);
}

// ---------------- final linear: out = h2 @ Wl^T + bl  (H2=16 -> P=12) ----------------
__global__ void final_linear_kernel(const float* __restrict__ Wl,
                                    const float* __restrict__ bl,
                                    float* __restrict__ out) {
    int i = blockIdx.x * blockDim.x + threadIdx.x;
    if (i >= NN * 12) return;
    int n = i / 12;
    int p = i % 12;
    float sacc = bl[p];
    #pragma unroll
    for (int c = 0; c < 16; c++) sacc = fmaf(g_h2[n * 16 + c], Wl[p * 16 + c], sacc);
    out[i] = sacc;
}

// ---------------- host orchestration: kernel launches ONLY ----------------
extern "C" void kernel_launch(void* const* d_in, const int* in_sizes, int n_in,
                              void* d_out, int out_size) {
    const float* x   = (const float*)d_in[0];
    const int*   ei  = (const int*)d_in[1];    // int32 view; dtype detected on device
    const float* ew  = (const float*)d_in[2];
    const float* Wx1 = (const float*)d_in[3];
    const float* bx1 = (const float*)d_in[4];
    const float* bh1 = (const float*)d_in[6];
    const float* Wx2 = (const float*)d_in[7];
    const float* bx2 = (const float*)d_in[8];
    const float* bh2 = (const float*)d_in[10];
    const float* Wl  = (const float*)d_in[11];
    const float* bl  = (const float*)d_in[12];
    float* out = (float*)d_out;

    const int EB = (EE + 255) / 256;      // 6250
    const int NB = (NN + 255) / 256;      // 196
    const int WB = (NN * 32 + 255) / 256; // 6250 (warp-per-node kernels)

    detect_kernel<<<1, 256>>>(ei);
    zero_init_kernel<<<NB, 256>>>();
    edge_deg_kernel<<<EB, 256>>>(ei, ew);
    node_dis_kernel<<<NB, 256>>>();
    edge_wn_kernel<<<EB, 256>>>(ew);
    scan_kernel<<<1, 1024>>>();
    edge_fill_kernel<<<EB, 256>>>();

    // ---- cell 1: v = x (ext), Fin=32, FO=32, h out -> sel 5 (g_h1) ----
    {
        const int FO = 32;
        const int sz = 32 * FO;
        const float* Wz = Wx1 + (0 * KCH) * sz;
        const float* Wh = Wx1 + (2 * KCH) * sz;
        gemm0_kernel<<<WB, 256>>>(x, -1, Wz, Wh,
                                  bx1 + 0, bh1 + 0, bx1 + 2 * FO, bh1 + 2 * FO, FO);
        spmm_gate_kernel<<<WB, 256>>>(x, -1, x, -2, 1, Wz + 1 * sz, Wh + 1 * sz, FO);
        spmm_gate_kernel<<<WB, 256>>>(x,  1, x, -1, 2, Wz + 2 * sz, Wh + 2 * sz, FO);
        spmm_gate_kernel<<<WB, 256>>>(x,  2, x,  1, 0, Wz + 3 * sz, Wh + 3 * sz, FO);
        spmm_gate_kernel<<<WB, 256>>>(x,  0, x,  2, 1, Wz + 4 * sz, Wh + 4 * sz, FO);
        gate_final_kernel<<<(NN * FO + 255) / 256, 256>>>(5, NN * FO);
    }
    // ---- cell 2: v = g_h1 (sel 5), Fin=32, FO=16, h out -> sel 6 (g_h2) ----
    {
        const int FO = 16;
        const int sz = 32 * FO;
        const float* Wz = Wx2 + (0 * KCH) * sz;
        const float* Wh = Wx2 + (2 * KCH) * sz;
        gemm0_kernel<<<WB, 256>>>(x, 5, Wz, Wh,
                                  bx2 + 0, bh2 + 0, bx2 + 2 * FO, bh2 + 2 * FO, FO);
        spmm_gate_kernel<<<WB, 256>>>(x, 5, x, -2, 1, Wz + 1 * sz, Wh + 1 * sz, FO);
        spmm_gate_kernel<<<WB, 256>>>(x, 1, x,  5, 2, Wz + 2 * sz, Wh + 2 * sz, FO);
        spmm_gate_kernel<<<WB, 256>>>(x, 2, x,  1, 0, Wz + 3 * sz, Wh + 3 * sz, FO);
        spmm_gate_kernel<<<WB, 256>>>(x, 0, x,  2, 1, Wz + 4 * sz, Wh + 4 * sz, FO);
        gate_final_kernel<<<(NN * FO + 255) / 256, 256>>>(6, NN * FO);
    }
    final_linear_kernel<<<(NN * 12 + 255) / 256, 256>>>(Wl, bl, out);
}

// round 17
// speedup vs baseline: 1.2494x; 1.2494x over previous
#include <cuda_runtime.h>
#include <cuda_bf16.h>
#include <math.h>

#define NN 50000
#define EE 1600000
#define KCH 5

// ---------------- static scratch (no runtime allocation) ----------------
__device__ int   g_is64;           // edge_index dtype flag (detected on device)
__device__ float g_deg[NN];        // degree -> rsqrt(deg) in-place
__device__ int   g_cnt[NN];        // histogram of in-degree (by col)
__device__ int   g_fill[NN];       // fill cursors for CSR scatter
__device__ int   g_ptr[NN + 1];    // CSR row (target) pointers
__device__ int   g_r32[EE];        // edge source (int32)
__device__ int   g_c32[EE];        // edge target (int32)
__device__ int2  g_edge[EE];       // CSR: packed (source row, weight-as-int) per entry
__device__ float g_T0[NN * 32];
__device__ float g_T1[NN * 32];
__device__ float g_T2[NN * 32];
__device__ float g_Az[NN * 32];
__device__ float g_Ah[NN * 32];
__device__ float g_h1[NN * 32];
__device__ float g_h2[NN * 16];

static const unsigned FULL = 0xFFFFFFFFu;

// selector -> device buffer (avoids host symbol queries)
__device__ __forceinline__ float* selbuf(int s) {
    switch (s) {
        case 0: return g_T0;
        case 1: return g_T1;
        case 2: return g_T2;
        case 5: return g_h1;
        case 6: return g_h2;
    }
    return g_T0;
}

// ---------------- dtype detection: int64 edge_index has all-zero odd words ----
__global__ void detect_kernel(const int* __restrict__ ei32) {
    __shared__ int snz;
    if (threadIdx.x == 0) snz = 0;
    __syncthreads();
    int v = 0;
    for (int i = threadIdx.x; i < 65536; i += blockDim.x) v |= ei32[2 * i + 1];
    if (v) atomicOr(&snz, 1);
    __syncthreads();
    if (threadIdx.x == 0) g_is64 = (snz == 0) ? 1 : 0;
}

// ---------------- zero-init (graph-safe) ----------------
__global__ void zero_init_kernel() {
    int i = blockIdx.x * blockDim.x + threadIdx.x;
    if (i < NN) {
        g_deg[i]  = 0.0f;
        g_cnt[i]  = 0;
        g_fill[i] = 0;
    }
}

// ---------------- edge preprocessing (deg + histogram fused) ----------------
__global__ void edge_deg_kernel(const int* __restrict__ ei32,
                                const float* __restrict__ ew) {
    int e = blockIdx.x * blockDim.x + threadIdx.x;
    if (e >= EE) return;
    int r, c;
    if (g_is64) {   // int64 little-endian: value in even word
        r = ei32[2 * e];
        c = ei32[2 * (EE + e)];
    } else {        // int32
        r = ei32[e];
        c = ei32[EE + e];
    }
    r = min(max(r, 0), NN - 1);
    c = min(max(c, 0), NN - 1);
    g_r32[e] = r;
    g_c32[e] = c;
    atomicAdd(&g_deg[r], ew[e]);
    atomicAdd(&g_cnt[c], 1);
}

__global__ void node_dis_kernel() {
    int n = blockIdx.x * blockDim.x + threadIdx.x;
    if (n >= NN) return;
    float d = g_deg[n];
    g_deg[n] = (d > 0.0f) ? rsqrtf(d) : 0.0f;
}

// single-block exclusive scan over g_cnt -> g_ptr (warp-shuffle based)
__global__ void scan_kernel() {
    __shared__ int wsum[32];
    __shared__ int carry_s;
    int tid = threadIdx.x, lane = tid & 31, wid = tid >> 5;
    if (tid == 0) carry_s = 0;
    __syncthreads();
    for (int base = 0; base < NN; base += 1024) {
        int i = base + tid;
        int v = (i < NN) ? g_cnt[i] : 0;
        int x = v;
        #pragma unroll
        for (int off = 1; off < 32; off <<= 1) {
            int t = __shfl_up_sync(FULL, x, off);
            if (lane >= off) x += t;
        }
        if (lane == 31) wsum[wid] = x;
        __syncthreads();
        if (wid == 0) {
            int y = wsum[lane];
            #pragma unroll
            for (int off = 1; off < 32; off <<= 1) {
                int t = __shfl_up_sync(FULL, y, off);
                if (lane >= off) y += t;
            }
            wsum[lane] = y;
        }
        __syncthreads();
        int incl = x + (wid > 0 ? wsum[wid - 1] : 0) + carry_s;
        if (i < NN) g_ptr[i + 1] = incl;
        __syncthreads();
        if (tid == 1023) carry_s = incl;
        __syncthreads();
    }
    if (tid == 0) g_ptr[0] = 0;
}

// fill CSR + compute normalized weight inline (wn pass fused away)
__global__ void edge_fill_kernel(const float* __restrict__ ew) {
    int e = blockIdx.x * blockDim.x + threadIdx.x;
    if (e >= EE) return;
    int r = g_r32[e];
    int c = g_c32[e];
    int pos = g_ptr[c] + atomicAdd(&g_fill[c], 1);
    float wn = -g_deg[r] * ew[e] * g_deg[c];
    g_edge[pos] = make_int2(r, __float_as_int(wn));
}

// ---------------- shared SpMM row helper: smem-staged edges, 8-way MLP gathers ----
__device__ __forceinline__ float spmm_row(const float* __restrict__ Tin,
                                          int s, int e, int lane, int2* sE) {
    float acc = 0.0f;
    for (int base = s; base < e; base += 32) {
        int idx = base + lane;
        int2 ed = make_int2(0, 0);            // pad: sr=0, w=+0.0f
        if (idx < e) ed = g_edge[idx];
        sE[lane] = ed;
        __syncwarp();
        int mr = (min(32, e - base) + 7) & ~7;
        for (int j = 0; j < mr; j += 8) {
            int2 e0 = sE[j + 0];
            int2 e1 = sE[j + 1];
            int2 e2 = sE[j + 2];
            int2 e3 = sE[j + 3];
            int2 e4 = sE[j + 4];
            int2 e5 = sE[j + 5];
            int2 e6 = sE[j + 6];
            int2 e7 = sE[j + 7];
            float v0 = Tin[e0.x * 32 + lane];
            float v1 = Tin[e1.x * 32 + lane];
            float v2 = Tin[e2.x * 32 + lane];
            float v3 = Tin[e3.x * 32 + lane];
            float v4 = Tin[e4.x * 32 + lane];
            float v5 = Tin[e5.x * 32 + lane];
            float v6 = Tin[e6.x * 32 + lane];
            float v7 = Tin[e7.x * 32 + lane];
            acc = fmaf(__int_as_float(e0.y), v0, acc);
            acc = fmaf(__int_as_float(e1.y), v1, acc);
            acc = fmaf(__int_as_float(e2.y), v2, acc);
            acc = fmaf(__int_as_float(e3.y), v3, acc);
            acc = fmaf(__int_as_float(e4.y), v4, acc);
            acc = fmaf(__int_as_float(e5.y), v5, acc);
            acc = fmaf(__int_as_float(e6.y), v6, acc);
            acc = fmaf(__int_as_float(e7.y), v7, acc);
        }
        __syncwarp();
    }
    return acc;
}

// ---------------- first SpMM of a cell: fused k=0 GEMM + k=1 SpMM+GEMM ----------------
// Az = b_z + t0@Wz0 + T1@Wz1 ; Ah = b_h + t0@Wh0 + T1@Wh1 ; Tout(sel 1) = T1 = L@Tin
__global__ __launch_bounds__(256) void spmm_first_kernel(
    const float* __restrict__ TinExt, int selTin,
    const float* __restrict__ Wz0, const float* __restrict__ Wh0,
    const float* __restrict__ Wz1, const float* __restrict__ Wh1,
    const float* __restrict__ bxz, const float* __restrict__ bhz,
    const float* __restrict__ bxh, const float* __restrict__ bhh, int FO) {
    __shared__ float sWz0[1024], sWh0[1024], sWz1[1024], sWh1[1024];
    __shared__ int2  sEdge[8][32];
    const float* Tin = (selTin < 0) ? TinExt : selbuf(selTin);
    int tid = threadIdx.x;
    for (int i = tid; i < 32 * FO; i += blockDim.x) {
        sWz0[i] = Wz0[i]; sWh0[i] = Wh0[i]; sWz1[i] = Wz1[i]; sWh1[i] = Wh1[i];
    }
    __syncthreads();
    int warp = (blockIdx.x * blockDim.x + tid) >> 5;
    int lane = tid & 31;
    if (warp >= NN) return;
    int s = g_ptr[warp];
    int e = g_ptr[warp + 1];
    float t0 = Tin[warp * 32 + lane];
    float t1 = spmm_row(Tin, s, e, lane, sEdge[(tid >> 5) & 7]);
    g_T1[warp * 32 + lane] = t1;
    float az = 0.0f, ah = 0.0f;
    #pragma unroll
    for (int fi = 0; fi < 32; fi++) {
        float u0 = __shfl_sync(FULL, t0, fi);
        float u1 = __shfl_sync(FULL, t1, fi);
        az = fmaf(u0, sWz0[fi * FO + lane], az);
        ah = fmaf(u0, sWh0[fi * FO + lane], ah);
        az = fmaf(u1, sWz1[fi * FO + lane], az);
        ah = fmaf(u1, sWh1[fi * FO + lane], ah);
    }
    if (lane < FO) {
        g_Az[warp * FO + lane] = az + bxz[lane] + bhz[lane];
        g_Ah[warp * FO + lane] = ah + bxh[lane] + bhh[lane];
    }
}

// ---------------- subsequent SpMM (k>=2): Tnew = 2*(L@Tin) - Tprev + gate accum ----
__global__ __launch_bounds__(256) void spmm_gate_kernel(
    const float* __restrict__ TinExt, int selTin,
    const float* __restrict__ PrevExt, int selPrev, int selOut,
    const float* __restrict__ Wz, const float* __restrict__ Wh, int FO) {
    __shared__ float sWz[1024], sWh[1024];
    __shared__ int2  sEdge[8][32];
    const float* Tin  = (selTin < 0) ? TinExt : selbuf(selTin);
    float*       Tout = selbuf(selOut);
    int tid = threadIdx.x;
    for (int i = tid; i < 32 * FO; i += blockDim.x) { sWz[i] = Wz[i]; sWh[i] = Wh[i]; }
    __syncthreads();
    int warp = (blockIdx.x * blockDim.x + tid) >> 5;
    int lane = tid & 31;
    if (warp >= NN) return;
    int s = g_ptr[warp];
    int e = g_ptr[warp + 1];
    float acc = spmm_row(Tin, s, e, lane, sEdge[(tid >> 5) & 7]);
    const float* Tprev = (selPrev < 0) ? PrevExt : selbuf(selPrev);
    float tnew = 2.0f * acc - Tprev[warp * 32 + lane];
    Tout[warp * 32 + lane] = tnew;
    float az = 0.0f, ah = 0.0f;
    #pragma unroll
    for (int fi = 0; fi < 32; fi++) {
        float v = __shfl_sync(FULL, tnew, fi);
        az = fmaf(v, sWz[fi * FO + lane], az);
        ah = fmaf(v, sWh[fi * FO + lane], ah);
    }
    if (lane < FO) {
        g_Az[warp * FO + lane] += az;
        g_Ah[warp * FO + lane] += ah;
    }
}

// ---------------- gate nonlinearity: h = relu((1-sigmoid(Az)) * tanh(Ah)) ----------------
__global__ void gate_final_kernel(int selOut, int total) {
    int i = blockIdx.x * blockDim.x + threadIdx.x;
    if (i >= total) return;
    float* h = selbuf(selOut);
    float z = 1.0f / (1.0f + expf(-g_Az[i]));
    float v = (1.0f - z) * tanhf(g_Ah[i]);
    h[i] = fmaxf(v, 0.0f);
}

// ---------------- final linear: out = h2 @ Wl^T + bl  (H2=16 -> P=12) ----------------
__global__ void final_linear_kernel(const float* __restrict__ Wl,
                                    const float* __restrict__ bl,
                                    float* __restrict__ out) {
    int i = blockIdx.x * blockDim.x + threadIdx.x;
    if (i >= NN * 12) return;
    int n = i / 12;
    int p = i % 12;
    float sacc = bl[p];
    #pragma unroll
    for (int c = 0; c < 16; c++) sacc = fmaf(g_h2[n * 16 + c], Wl[p * 16 + c], sacc);
    out[i] = sacc;
}

// ---------------- host orchestration: kernel launches ONLY ----------------
extern "C" void kernel_launch(void* const* d_in, const int* in_sizes, int n_in,
                              void* d_out, int out_size) {
    const float* x   = (const float*)d_in[0];
    const int*   ei  = (const int*)d_in[1];    // int32 view; dtype detected on device
    const float* ew  = (const float*)d_in[2];
    const float* Wx1 = (const float*)d_in[3];
    const float* bx1 = (const float*)d_in[4];
    const float* bh1 = (const float*)d_in[6];
    const float* Wx2 = (const float*)d_in[7];
    const float* bx2 = (const float*)d_in[8];
    const float* bh2 = (const float*)d_in[10];
    const float* Wl  = (const float*)d_in[11];
    const float* bl  = (const float*)d_in[12];
    float* out = (float*)d_out;

    const int EB = (EE + 255) / 256;      // 6250
    const int NB = (NN + 255) / 256;      // 196
    const int WB = (NN * 32 + 255) / 256; // 6250 (warp-per-node kernels)

    detect_kernel<<<1, 256>>>(ei);
    zero_init_kernel<<<NB, 256>>>();
    edge_deg_kernel<<<EB, 256>>>(ei, ew);
    node_dis_kernel<<<NB, 256>>>();
    scan_kernel<<<1, 1024>>>();
    edge_fill_kernel<<<EB, 256>>>(ew);

    // ---- cell 1: v = x (ext), Fin=32, FO=32, h out -> sel 5 (g_h1) ----
    {
        const int FO = 32;
        const int sz = 32 * FO;
        const float* Wz = Wx1 + (0 * KCH) * sz;   // gate z x-conv weights (K blocks)
        const float* Wh = Wx1 + (2 * KCH) * sz;   // gate h x-conv weights (K blocks)
        spmm_first_kernel<<<WB, 256>>>(x, -1, Wz, Wh, Wz + 1 * sz, Wh + 1 * sz,
                                       bx1 + 0, bh1 + 0, bx1 + 2 * FO, bh1 + 2 * FO, FO);
        spmm_gate_kernel<<<WB, 256>>>(x, 1, x, -1, 2, Wz + 2 * sz, Wh + 2 * sz, FO);
        spmm_gate_kernel<<<WB, 256>>>(x, 2, x,  1, 0, Wz + 3 * sz, Wh + 3 * sz, FO);
        spmm_gate_kernel<<<WB, 256>>>(x, 0, x,  2, 1, Wz + 4 * sz, Wh + 4 * sz, FO);
        gate_final_kernel<<<(NN * FO + 255) / 256, 256>>>(5, NN * FO);
    }
    // ---- cell 2: v = g_h1 (sel 5), Fin=32, FO=16, h out -> sel 6 (g_h2) ----
    {
        const int FO = 16;
        const int sz = 32 * FO;
        const float* Wz = Wx2 + (0 * KCH) * sz;
        const float* Wh = Wx2 + (2 * KCH) * sz;
        spmm_first_kernel<<<WB, 256>>>(x, 5, Wz, Wh, Wz + 1 * sz, Wh + 1 * sz,
                                       bx2 + 0, bh2 + 0, bx2 + 2 * FO, bh2 + 2 * FO, FO);
        spmm_gate_kernel<<<WB, 256>>>(x, 1, x,  5, 2, Wz + 2 * sz, Wh + 2 * sz, FO);
        spmm_gate_kernel<<<WB, 256>>>(x, 2, x,  1, 0, Wz + 3 * sz, Wh + 3 * sz, FO);
        spmm_gate_kernel<<<WB, 256>>>(x, 0, x,  2, 1, Wz + 4 * sz, Wh + 4 * sz, FO);
        gate_final_kernel<<<(NN * FO + 255) / 256, 256>>>(6, NN * FO);
    }
    final_linear_kernel<<<(NN * 12 + 255) / 256, 256>>>(Wl, bl, out);
}